// round 15
// baseline (speedup 1.0000x reference)
#include <cuda_runtime.h>
#include <cuda_bf16.h>
#include <cuda_fp16.h>
#include <math.h>
#include <stdint.h>

// Problem constants
#define B_   2
#define T_   2048
#define C_   1024
#define H_   16
#define G_   4
#define DQK_ 64
#define DV_  128
#define NT_  (B_ * T_)        // 4096 tokens
#define NQKV (H_*DQK_ + G_*DQK_ + G_*DV_)   // 1792
#define KOFF (H_*DQK_)        // 1024
#define VOFF (H_*DQK_ + G_*DQK_) // 1280
#define LOG2E_ 1.4426950408889634f

// ---------------------------------------------------------------------------
// Device scratch (no cudaMalloc allowed)
// ---------------------------------------------------------------------------
__device__ __half g_xh[(size_t)NT_ * C_];      // x split-fp16 hi
__device__ __half g_xl[(size_t)NT_ * C_];      // x split-fp16 lo
__device__ __half g_wth[(size_t)NQKV * C_];    // packed W^T [1792][1024] fp16
__device__ __half g_yh[(size_t)NT_ * DV_];     // head-summed attn out hi
__device__ __half g_yl[(size_t)NT_ * DV_];     // lo
__device__ __half g_pth[(size_t)C_ * DV_];     // Wproj^T [1024][128] fp16
__device__ float  g_qkv[(size_t)NT_ * NQKV];   // fused projection (fp32)
__device__ __half g_qkvh[(size_t)NT_ * NQKV];  // fp16 q(roped)/k(roped)/v
__device__ float  g_yp[(size_t)H_ * NT_ * DV_];// per-head attn output
__device__ float2 g_rope[(size_t)T_ * 32];     // (cos,sin) per (t,lane)

// ---------------------------------------------------------------------------
// mma.sync / ldmatrix / cp.async helpers (sm_80+ PTX; valid on compute_103)
// ---------------------------------------------------------------------------
__device__ __forceinline__ void mma_f16(float& d0, float& d1, float& d2, float& d3,
    uint32_t a0, uint32_t a1, uint32_t a2, uint32_t a3, uint32_t b0, uint32_t b1)
{
    asm volatile(
        "mma.sync.aligned.m16n8k16.row.col.f32.f16.f16.f32 "
        "{%0,%1,%2,%3},{%4,%5,%6,%7},{%8,%9},{%0,%1,%2,%3};"
        : "+f"(d0), "+f"(d1), "+f"(d2), "+f"(d3)
        : "r"(a0), "r"(a1), "r"(a2), "r"(a3), "r"(b0), "r"(b1));
}

__device__ __forceinline__ void ldsm_x4(uint32_t& r0, uint32_t& r1,
                                        uint32_t& r2, uint32_t& r3, uint32_t a)
{
    asm volatile("ldmatrix.sync.aligned.m8n8.x4.shared.b16 {%0,%1,%2,%3}, [%4];"
                 : "=r"(r0), "=r"(r1), "=r"(r2), "=r"(r3) : "r"(a));
}

__device__ __forceinline__ void ldsm_x4_t(uint32_t& r0, uint32_t& r1,
                                          uint32_t& r2, uint32_t& r3, uint32_t a)
{
    asm volatile("ldmatrix.sync.aligned.m8n8.x4.trans.shared.b16 {%0,%1,%2,%3}, [%4];"
                 : "=r"(r0), "=r"(r1), "=r"(r2), "=r"(r3) : "r"(a));
}

__device__ __forceinline__ uint32_t smem_u32(const void* p) {
    uint32_t a;
    asm("{ .reg .u64 t; cvta.to.shared.u64 t, %1; cvt.u32.u64 %0, t; }"
        : "=r"(a) : "l"(p));
    return a;
}

// pack (lo,hi) floats to f16x2 then exp2 in fp16 (MUFU.EX2 on both halves)
__device__ __forceinline__ uint32_t exp2_pack(float lo, float hi) {
    uint32_t r;
    asm("cvt.rn.f16x2.f32 %0, %1, %2;" : "=r"(r) : "f"(hi), "f"(lo));
    asm("ex2.approx.f16x2 %0, %0;" : "+r"(r));
    return r;
}

#define CP_ASYNC16(dst, src) \
    asm volatile("cp.async.cg.shared.global [%0], [%1], 16;" \
                 :: "r"(dst), "l"(src) : "memory")
#define CP_COMMIT() asm volatile("cp.async.commit_group;" ::: "memory")
#define CP_WAIT(n)  asm volatile("cp.async.wait_group %0;" :: "n"(n) : "memory")

// ---------------------------------------------------------------------------
// Split-fp16 GEMM (2-pass): C[M,N] = (Ah+Al)[M,K] @ Bh[N,K]^T
// 3 tiles/stage, 4-stage cp.async pipeline, XOR swizzle, one sync/stage,
// 2 CTAs/SM.
// ---------------------------------------------------------------------------
#define MM_TILE_B (128 * 64)                   // 8192 bytes per tile
#define MM_STAGE_B (3 * MM_TILE_B)             // 24576 per stage
#define MM_SMEM_BYTES (4 * MM_STAGE_B)         // 98304

__global__ __launch_bounds__(256, 2) void mm_gemm(
    const __half* __restrict__ Ah, const __half* __restrict__ Al,
    const __half* __restrict__ Bh,
    float* __restrict__ Cout, __half* __restrict__ Hout, int K, int ldc)
{
    extern __shared__ __half smd[];

    const int tid  = threadIdx.x;
    const int wid  = tid >> 5;
    const int lane = tid & 31;
    const int g8   = lane >> 2;
    const int t4   = lane & 3;
    const int m0   = blockIdx.y * 128;
    const int n0   = blockIdx.x * 128;
    const int ms   = wid & 3;
    const int ws   = wid >> 2;

    const int lrow  = (lane & 7) + ((lane >> 3) & 1) * 8;
    const int lcol8 = (lane >> 4) * 8;

    const __half* srcs[3] = {
        Ah + (size_t)m0 * K, Al + (size_t)m0 * K, Bh + (size_t)n0 * K };

    const int f_row = tid >> 2;
    const int f_ch  = tid & 3;

    uint32_t dsto[6];
    #pragma unroll
    for (int t = 0; t < 6; ++t) {
        const int tl  = t >> 1;
        const int row = ((t & 1) << 6) + f_row;
        const int cs  = f_ch ^ ((row >> 1) & 3);
        dsto[t] = (uint32_t)(((tl * 128 + row) * 32 + cs * 8) * 2);
    }
    const uint32_t smb0 = smem_u32(smd);

    auto issue_stage = [&](int s, int st) {
        const int k0 = s << 5;
        const uint32_t base = smb0 + (uint32_t)st * MM_STAGE_B;
        #pragma unroll
        for (int t = 0; t < 6; ++t) {
            const int tl  = t >> 1;
            const int row = ((t & 1) << 6) + f_row;
            const __half* src = srcs[tl] + (size_t)row * K + k0 + f_ch * 8;
            CP_ASYNC16(base + dsto[t], src);
        }
        CP_COMMIT();
    };

    float acc[2][8][4];
    #pragma unroll
    for (int mf = 0; mf < 2; mf++)
        #pragma unroll
        for (int nf = 0; nf < 8; nf++)
            #pragma unroll
            for (int i = 0; i < 4; i++) acc[mf][nf][i] = 0.f;

    const int nst = K >> 5;
    issue_stage(0, 0);
    if (nst > 1) issue_stage(1, 1);
    if (nst > 2) issue_stage(2, 2);

    int st = 0;
    for (int s = 0; s < nst; ++s) {
        if (s + 2 < nst)      CP_WAIT(2);
        else if (s + 1 < nst) CP_WAIT(1);
        else                  CP_WAIT(0);
        __syncthreads();
        if (s + 3 < nst) issue_stage(s + 3, (st + 3) & 3);

        const uint32_t smb = smb0 + (uint32_t)st * MM_STAGE_B;

        #pragma unroll
        for (int ks = 0; ks < 2; ++ks) {
            const int cb = ks * 2 + (lcol8 >> 3);

            uint32_t ah[2][4], al[2][4];
            #pragma unroll
            for (int mf = 0; mf < 2; ++mf) {
                const int row = ms * 32 + mf * 16 + lrow;
                const uint32_t off = (uint32_t)(row * 64
                                   + ((cb ^ ((row >> 1) & 3)) << 4));
                ldsm_x4(ah[mf][0], ah[mf][1], ah[mf][2], ah[mf][3],
                        smb + 0 * MM_TILE_B + off);
                ldsm_x4(al[mf][0], al[mf][1], al[mf][2], al[mf][3],
                        smb + 1 * MM_TILE_B + off);
            }

            #pragma unroll
            for (int np = 0; np < 4; ++np) {
                const int row = ws * 64 + np * 16 + lrow;
                const uint32_t off = (uint32_t)(row * 64
                                   + ((cb ^ ((row >> 1) & 3)) << 4));
                uint32_t bh[4];
                ldsm_x4(bh[0], bh[1], bh[2], bh[3], smb + 2 * MM_TILE_B + off);
                #pragma unroll
                for (int e = 0; e < 2; ++e) {
                    const int nf = np * 2 + e;
                    const uint32_t bh0 = bh[e], bh1 = bh[2 + e];
                    #pragma unroll
                    for (int mf = 0; mf < 2; ++mf) {
                        float* d = acc[mf][nf];
                        mma_f16(d[0], d[1], d[2], d[3],
                                ah[mf][0], ah[mf][1], ah[mf][2], ah[mf][3],
                                bh0, bh1);
                        mma_f16(d[0], d[1], d[2], d[3],
                                al[mf][0], al[mf][1], al[mf][2], al[mf][3],
                                bh0, bh1);
                    }
                }
            }
        }
        st = (st + 1) & 3;
    }

    #pragma unroll
    for (int mf = 0; mf < 2; ++mf) {
        const int r = m0 + ms * 32 + mf * 16 + g8;
        #pragma unroll
        for (int nf = 0; nf < 8; ++nf) {
            const int c = n0 + ws * 64 + nf * 8 + 2 * t4;
            *(float2*)(Cout + (size_t)r * ldc + c) =
                make_float2(acc[mf][nf][0], acc[mf][nf][1]);
            *(float2*)(Cout + (size_t)(r + 8) * ldc + c) =
                make_float2(acc[mf][nf][2], acc[mf][nf][3]);
            if (Hout) {
                *(__half2*)(Hout + (size_t)r * ldc + c) =
                    __floats2half2_rn(acc[mf][nf][0], acc[mf][nf][1]);
                *(__half2*)(Hout + (size_t)(r + 8) * ldc + c) =
                    __floats2half2_rn(acc[mf][nf][2], acc[mf][nf][3]);
            }
        }
    }
}

// ---------------------------------------------------------------------------
// Fused prep kernel (ONE launch): rope table + x split-fp16 + W^T pack.
// ---------------------------------------------------------------------------
#define PREP_ROPE_BLKS 256                       // T_*32/256
#define PREP_CVT_BLKS  4096                      // NT_*C_/4/256
#define PREP_PACK_BLKS ((C_/32)*(NQKV/32))       // 1792

__global__ void prep_all(const float* __restrict__ x,
                         const float* __restrict__ Wq,
                         const float* __restrict__ Wk,
                         const float* __restrict__ Wv)
{
    __shared__ float tile[32][33];
    const int bid = blockIdx.x;
    const int tid = threadIdx.x;

    if (bid < PREP_ROPE_BLKS) {
        const int i = bid * 256 + tid;
        const int t = i >> 5, lane = i & 31;
        const float inv = __expf(-(float)lane * 0.28782313662425574f);
        const float ang = (float)t * inv;
        float s, c;
        sincosf(ang, &s, &c);
        g_rope[i] = make_float2(c, s);
    } else if (bid < PREP_ROPE_BLKS + PREP_CVT_BLKS) {
        const int i = (bid - PREP_ROPE_BLKS) * 256 + tid;
        const float4 v = ((const float4*)x)[i];
        const __half h0 = __float2half(v.x);
        const __half h1 = __float2half(v.y);
        const __half h2 = __float2half(v.z);
        const __half h3 = __float2half(v.w);
        ((__half2*)g_xh)[2*i]   = __half2(h0, h1);
        ((__half2*)g_xh)[2*i+1] = __half2(h2, h3);
        ((__half2*)g_xl)[2*i] = __half2(
            __float2half(v.x - __half2float(h0)),
            __float2half(v.y - __half2float(h1)));
        ((__half2*)g_xl)[2*i+1] = __half2(
            __float2half(v.z - __half2float(h2)),
            __float2half(v.w - __half2float(h3)));
    } else {
        const int flat = bid - (PREP_ROPE_BLKS + PREP_CVT_BLKS);
        const int bx = flat % (C_ / 32);
        const int by = flat / (C_ / 32);
        const int tx = tid & 31, ty = tid >> 5;
        const int k0 = bx * 32;
        const int n0 = by * 32;

        const float* W; int nw, noff;
        if (n0 < KOFF)      { W = Wq; nw = H_*DQK_; noff = n0; }
        else if (n0 < VOFF) { W = Wk; nw = G_*DQK_; noff = n0 - KOFF; }
        else                { W = Wv; nw = G_*DV_;  noff = n0 - VOFF; }

        #pragma unroll
        for (int j = 0; j < 4; ++j)
            tile[ty + j * 8][tx] = W[(size_t)(k0 + ty + j * 8) * nw + noff + tx];
        __syncthreads();
        #pragma unroll
        for (int j = 0; j < 4; ++j)
            g_wth[(size_t)(n0 + ty + j * 8) * C_ + k0 + tx] =
                __float2half(tile[tx][ty + j * 8]);
    }
}

__global__ void pack_pt(const float* __restrict__ Wp)
{
    const int i = blockIdx.x * blockDim.x + threadIdx.x;
    if (i >= C_ * DV_) return;
    const int nn = i / DV_;
    const int k  = i % DV_;
    g_pth[i] = __float2half(Wp[(size_t)k * C_ + nn]);
}

__global__ void sum_split_y()
{
    const int i = blockIdx.x * blockDim.x + threadIdx.x;
    if (i >= (NT_ * DV_) / 4) return;
    float4 s = make_float4(0.f, 0.f, 0.f, 0.f);
    #pragma unroll
    for (int h = 0; h < H_; ++h) {
        const float4 v = ((const float4*)(g_yp + (size_t)h * NT_ * DV_))[i];
        s.x += v.x; s.y += v.y; s.z += v.z; s.w += v.w;
    }
    const __half h0 = __float2half(s.x);
    const __half h1 = __float2half(s.y);
    const __half h2 = __float2half(s.z);
    const __half h3 = __float2half(s.w);
    ((__half2*)g_yh)[2*i]   = __half2(h0, h1);
    ((__half2*)g_yh)[2*i+1] = __half2(h2, h3);
    ((__half2*)g_yl)[2*i] = __half2(
        __float2half(s.x - __half2float(h0)),
        __float2half(s.y - __half2float(h1)));
    ((__half2*)g_yl)[2*i+1] = __half2(
        __float2half(s.z - __half2float(h2)),
        __float2half(s.w - __half2float(h3)));
}

// ---------------------------------------------------------------------------
// RoPE + L2-norm; q scale folded with log2e (attention runs in exp2 domain).
// ---------------------------------------------------------------------------
__global__ void rope_norm_kernel(const float* __restrict__ qnf)
{
    const int warp = (blockIdx.x * blockDim.x + threadIdx.x) >> 5;
    const int lane = threadIdx.x & 31;
    if (warp >= NT_ * 20) return;
    const int token = warp / 20;
    const int slot  = warp % 20;
    const int t     = token & (T_ - 1);

    const size_t off = (size_t)token * NQKV
                     + ((slot < 16) ? slot * DQK_ : KOFF + (slot - 16) * DQK_);
    const float* src = g_qkv + off;
    __half* dst = g_qkvh + off;

    const float x0 = src[lane];
    const float x1 = src[lane + 32];

    const float2 cs = g_rope[(t << 5) + lane];
    const float c = cs.x, s = cs.y;

    const float r0 = x0 * c - x1 * s;
    const float r1 = x1 * c + x0 * s;

    float ss = r0 * r0 + r1 * r1;
    #pragma unroll
    for (int o = 16; o > 0; o >>= 1) ss += __shfl_xor_sync(0xFFFFFFFFu, ss, o);

    float scale = 1.f / (sqrtf(ss) + 1e-6f);
    if (slot < 16) scale *= qnf[0] * LOG2E_;

    dst[lane]      = __float2half(r0 * scale);
    dst[lane + 32] = __float2half(r1 * scale);
}

// ---------------------------------------------------------------------------
// Flash attention: FA2 register softmax (exp2 domain, f16x2 MUFU, ones-MMA
// sums, gated rescale), one sync/iter, cp.async double-buffered K/V,
// depth-1 software-pipelined PV ldmatrix. 128 thr / 4 warps, 3 CTAs/SM.
// ---------------------------------------------------------------------------
struct AttnSmem {
    __half Qs[64][72];
    __half Ks[2][64][72];
    __half Vs[2][64][136];
};
#define ATTN_SMEM ((int)sizeof(AttnSmem))

__global__ __launch_bounds__(128, 3) void attn_kernel(const float* __restrict__ lobo)
{
    extern __shared__ char smem_raw[];
    AttnSmem& S = *reinterpret_cast<AttnSmem*>(smem_raw);

    const int tid  = threadIdx.x;
    const int wid  = tid >> 5;
    const int lane = tid & 31;
    const int g8   = lane >> 2;
    const int t4   = lane & 3;

    const int qt = (gridDim.x - 1 - blockIdx.x);
    const int h  = blockIdx.y;
    const int b  = blockIdx.z;
    const int gq = h >> 2;
    const int q0 = qt * 64;
    const size_t tokbase = (size_t)b * T_;

    const int krow  = lane & 7;
    const int kcol8 = (lane >> 3) * 8;
    const int vrow  = (lane & 7) + ((lane >> 3) & 1) * 8;
    const int vcol8 = (lane >> 4) * 8;
    const uint32_t vbase = (uint32_t)((vrow * 136 + vcol8) * 2);

    #pragma unroll
    for (int i = 0; i < 16; ++i) {
        const int cid = tid + i * 128;
        const int row = cid >> 5;
        const int dp  = cid & 31;
        const uint32_t v = *(const uint32_t*)
            (g_qkvh + (tokbase + q0 + row) * NQKV + h * DQK_ + 2 * dp);
        *(uint32_t*)&S.Qs[row][2 * dp] = v;
    }

    const int rbase = (wid << 4);
    const int rg0 = q0 + rbase + g8;
    const int rg1 = rg0 + 8;

    float m0 = lobo[h] * LOG2E_, m1 = m0;
    float l0 = 1.f, l1 = 1.f;
    float o[16][4];
    #pragma unroll
    for (int nf = 0; nf < 16; nf++)
        #pragma unroll
        for (int i = 0; i < 4; i++) o[nf][i] = 0.f;

    uint32_t qf[4][4];
    const uint32_t ONES = 0x3C003C00u;

    const int nkt = qt + 1;

    auto issue_kv = [&](int kt) {
        const int st = kt & 1;
        const int k0 = kt * 64;
        #pragma unroll
        for (int j = 0; j < 4; ++j) {
            const int idx = tid + j * 128;
            const int row = idx >> 3, c = idx & 7;
            CP_ASYNC16(smem_u32(&S.Ks[st][row][c * 8]),
                g_qkvh + (tokbase + k0 + row) * NQKV + KOFF + gq * DQK_ + c * 8);
        }
        #pragma unroll
        for (int j = 0; j < 8; ++j) {
            const int idx = tid + j * 128;
            const int row = idx >> 4, c = idx & 15;
            CP_ASYNC16(smem_u32(&S.Vs[st][row][c * 8]),
                g_qkvh + (tokbase + k0 + row) * NQKV + VOFF + gq * DV_ + c * 8);
        }
        CP_COMMIT();
    };

    issue_kv(0);

    for (int kt = 0; kt < nkt; ++kt) {
        const int st = kt & 1;
        CP_WAIT(0);
        __syncthreads();
        if (kt + 1 < nkt) issue_kv(kt + 1);

        if (kt == 0) {
            #pragma unroll
            for (int kf = 0; kf < 4; ++kf) {
                const int cb = kf * 16 + 2 * t4;
                qf[kf][0] = *(const uint32_t*)&S.Qs[rbase + g8    ][cb];
                qf[kf][1] = *(const uint32_t*)&S.Qs[rbase + g8 + 8][cb];
                qf[kf][2] = *(const uint32_t*)&S.Qs[rbase + g8    ][cb + 8];
                qf[kf][3] = *(const uint32_t*)&S.Qs[rbase + g8 + 8][cb + 8];
            }
        }

        // --- S = Q K^T ---
        float s[8][4];
        #pragma unroll
        for (int nf = 0; nf < 8; nf++)
            #pragma unroll
            for (int i = 0; i < 4; i++) s[nf][i] = 0.f;

        const uint32_t ksb = smem_u32(&S.Ks[st][0][0]);
        #pragma unroll
        for (int kp = 0; kp < 2; ++kp) {
            #pragma unroll
            for (int nf = 0; nf < 8; ++nf) {
                uint32_t b0a, b1a, b0b, b1b;
                ldsm_x4(b0a, b1a, b0b, b1b,
                        ksb + (uint32_t)(((nf * 8 + krow) * 72
                                          + kp * 32 + kcol8) * 2));
                mma_f16(s[nf][0], s[nf][1], s[nf][2], s[nf][3],
                        qf[2*kp][0], qf[2*kp][1], qf[2*kp][2], qf[2*kp][3],
                        b0a, b1a);
                mma_f16(s[nf][0], s[nf][1], s[nf][2], s[nf][3],
                        qf[2*kp+1][0], qf[2*kp+1][1], qf[2*kp+1][2], qf[2*kp+1][3],
                        b0b, b1b);
            }
        }

        if (kt == nkt - 1) {   // diagonal tile
            const int k0 = kt * 64;
            #pragma unroll
            for (int nf = 0; nf < 8; ++nf) {
                const int c = k0 + nf * 8 + 2 * t4;
                if (c     > rg0) s[nf][0] = -1e30f;
                if (c + 1 > rg0) s[nf][1] = -1e30f;
                if (c     > rg1) s[nf][2] = -1e30f;
                if (c + 1 > rg1) s[nf][3] = -1e30f;
            }
        }

        float mx0 = -1e30f, mx1 = -1e30f;
        #pragma unroll
        for (int nf = 0; nf < 8; ++nf) {
            mx0 = fmaxf(mx0, fmaxf(s[nf][0], s[nf][1]));
            mx1 = fmaxf(mx1, fmaxf(s[nf][2], s[nf][3]));
        }
        mx0 = fmaxf(mx0, __shfl_xor_sync(0xFFFFFFFFu, mx0, 1));
        mx0 = fmaxf(mx0, __shfl_xor_sync(0xFFFFFFFFu, mx0, 2));
        mx1 = fmaxf(mx1, __shfl_xor_sync(0xFFFFFFFFu, mx1, 1));
        mx1 = fmaxf(mx1, __shfl_xor_sync(0xFFFFFFFFu, mx1, 2));

        const float mn0 = fmaxf(m0, mx0);
        const float mn1 = fmaxf(m1, mx1);
        const float cr0 = exp2f(m0 - mn0);
        const float cr1 = exp2f(m1 - mn1);
        m0 = mn0; m1 = mn1;

        uint32_t pa[8], pb[8];
        #pragma unroll
        for (int nf = 0; nf < 8; ++nf) {
            pa[nf] = exp2_pack(s[nf][0] - mn0, s[nf][1] - mn0);
            pb[nf] = exp2_pack(s[nf][2] - mn1, s[nf][3] - mn1);
        }

        // Row sums via ones-MMA
        float sf0 = 0.f, sf1 = 0.f, sf2 = 0.f, sf3 = 0.f;
        #pragma unroll
        for (int kf = 0; kf < 4; ++kf)
            mma_f16(sf0, sf1, sf2, sf3,
                    pa[2*kf], pb[2*kf], pa[2*kf+1], pb[2*kf+1], ONES, ONES);
        l0 = l0 * cr0 + sf0;
        l1 = l1 * cr1 + sf2;

        if (__ballot_sync(0xFFFFFFFFu, (cr0 < 1.f) || (cr1 < 1.f))) {
            #pragma unroll
            for (int nf = 0; nf < 16; ++nf) {
                o[nf][0] *= cr0; o[nf][1] *= cr0;
                o[nf][2] *= cr1; o[nf][3] *= cr1;
            }
        }

        // --- O += P V, depth-1 software-pipelined V-fragment loads ---
        {
            const uint32_t vsb = smem_u32(&S.Vs[st][0][0]) + vbase;
            uint32_t vf[2][4];
            ldsm_x4_t(vf[0][0], vf[0][1], vf[0][2], vf[0][3], vsb);  // (kf=0,np=0)
            #pragma unroll
            for (int kf = 0; kf < 4; ++kf) {
                const uint32_t a0 = pa[2 * kf];
                const uint32_t a1 = pb[2 * kf];
                const uint32_t a2 = pa[2 * kf + 1];
                const uint32_t a3 = pb[2 * kf + 1];
                #pragma unroll
                for (int np = 0; np < 8; ++np) {
                    const int idx = kf * 8 + np;
                    const int cur = idx & 1;
                    if (idx + 1 < 32) {
                        const int nkf = (idx + 1) >> 3;
                        const int nnp = (idx + 1) & 7;
                        ldsm_x4_t(vf[cur ^ 1][0], vf[cur ^ 1][1],
                                  vf[cur ^ 1][2], vf[cur ^ 1][3],
                                  vsb + (uint32_t)((nkf * 16 * 136
                                                    + nnp * 16) * 2));
                    }
                    mma_f16(o[2*np][0], o[2*np][1], o[2*np][2], o[2*np][3],
                            a0, a1, a2, a3, vf[cur][0], vf[cur][1]);
                    mma_f16(o[2*np+1][0], o[2*np+1][1], o[2*np+1][2],
                            o[2*np+1][3],
                            a0, a1, a2, a3, vf[cur][2], vf[cur][3]);
                }
            }
        }
    }

    {
        const float inv0 = 1.f / l0;
        const float inv1 = 1.f / l1;
        float* dst0 = g_yp + ((size_t)h * NT_ + tokbase + rg0) * DV_;
        float* dst1 = g_yp + ((size_t)h * NT_ + tokbase + rg1) * DV_;
        #pragma unroll
        for (int nf = 0; nf < 16; ++nf) {
            const int c = nf * 8 + 2 * t4;
            *(float2*)(dst0 + c) = make_float2(o[nf][0] * inv0, o[nf][1] * inv0);
            *(float2*)(dst1 + c) = make_float2(o[nf][2] * inv1, o[nf][3] * inv1);
        }
    }
}

// ---------------------------------------------------------------------------
// Launch (attn is the 4th launch -> lands in the ncu capture slot)
// ---------------------------------------------------------------------------
extern "C" void kernel_launch(void* const* d_in, const int* in_sizes, int n_in,
                              void* d_out, int out_size)
{
    const float* x     = (const float*)d_in[0];
    // d_in[1] = iter_num (unused)
    const float* Wq    = (const float*)d_in[2];
    const float* Wk    = (const float*)d_in[3];
    const float* Wv    = (const float*)d_in[4];
    const float* Wproj = (const float*)d_in[5];
    const float* lobo  = (const float*)d_in[6];
    const float* qnf   = (const float*)d_in[7];
    float* out = (float*)d_out;

    __half *xh, *xl, *wth, *yh, *yl, *pth, *qkvh_ptr;
    float *qkv_ptr;
    cudaGetSymbolAddress((void**)&xh, g_xh);
    cudaGetSymbolAddress((void**)&xl, g_xl);
    cudaGetSymbolAddress((void**)&wth, g_wth);
    cudaGetSymbolAddress((void**)&yh, g_yh);
    cudaGetSymbolAddress((void**)&yl, g_yl);
    cudaGetSymbolAddress((void**)&pth, g_pth);
    cudaGetSymbolAddress((void**)&qkv_ptr, g_qkv);
    cudaGetSymbolAddress((void**)&qkvh_ptr, g_qkvh);

    cudaFuncSetAttribute(mm_gemm, cudaFuncAttributeMaxDynamicSharedMemorySize,
                         MM_SMEM_BYTES);
    cudaFuncSetAttribute(attn_kernel, cudaFuncAttributeMaxDynamicSharedMemorySize,
                         ATTN_SMEM);

    // 1: fused prep (rope table + x split + W^T pack)
    prep_all<<<PREP_ROPE_BLKS + PREP_CVT_BLKS + PREP_PACK_BLKS, 256>>>(
        x, Wq, Wk, Wv);

    // 2: fused QKV projection -> fp32 g_qkv + fp16 mirror
    mm_gemm<<<dim3(NQKV / 128, NT_ / 128), 256, MM_SMEM_BYTES>>>(
        xh, xl, wth, qkv_ptr, qkvh_ptr, C_, NQKV);

    // 3: RoPE + qk-norm + logit scale (base-2) -> fp16 q/k
    rope_norm_kernel<<<(NT_ * 20) / 8, 256>>>(qnf);

    // 4: attention  (ncu capture slot)
    attn_kernel<<<dim3(T_ / 64, H_, B_), 128, ATTN_SMEM>>>(lobo);

    // 5-7: proj weight pack, head-sum, output projection
    pack_pt<<<(C_ * DV_ + 255) / 256, 256>>>(Wproj);
    sum_split_y<<<(NT_ * DV_ / 4 + 255) / 256, 256>>>();
    mm_gemm<<<dim3(C_ / 128, NT_ / 128), 256, MM_SMEM_BYTES>>>(
        yh, yl, pth, out, nullptr, DV_, C_);
}

// round 16
// speedup vs baseline: 1.0005x; 1.0005x over previous
#include <cuda_runtime.h>
#include <cuda_bf16.h>
#include <cuda_fp16.h>
#include <math.h>
#include <stdint.h>

// Problem constants
#define B_   2
#define T_   2048
#define C_   1024
#define H_   16
#define G_   4
#define DQK_ 64
#define DV_  128
#define NT_  (B_ * T_)        // 4096 tokens
#define NQKV (H_*DQK_ + G_*DQK_ + G_*DV_)   // 1792
#define KOFF (H_*DQK_)        // 1024
#define VOFF (H_*DQK_ + G_*DQK_) // 1280
#define LOG2E_ 1.4426950408889634f

// ---------------------------------------------------------------------------
// Device scratch (no cudaMalloc allowed)
// ---------------------------------------------------------------------------
__device__ __half g_xh[(size_t)NT_ * C_];      // x split-fp16 hi
__device__ __half g_xl[(size_t)NT_ * C_];      // x split-fp16 lo
__device__ __half g_wth[(size_t)NQKV * C_];    // packed W^T [1792][1024] fp16
__device__ __half g_yh[(size_t)NT_ * DV_];     // head-summed attn out hi
__device__ __half g_yl[(size_t)NT_ * DV_];     // lo
__device__ __half g_pth[(size_t)C_ * DV_];     // Wproj^T [1024][128] fp16
__device__ float  g_qkv[(size_t)NT_ * NQKV];   // fused projection (fp32)
__device__ __half g_qkvh[(size_t)NT_ * NQKV];  // fp16 q(roped)/k(roped)/v
__device__ float  g_yp[(size_t)H_ * NT_ * DV_];// per-head attn output
__device__ float2 g_rope[(size_t)T_ * 32];     // (cos,sin) per (t,lane)

// ---------------------------------------------------------------------------
// mma.sync / ldmatrix / cp.async helpers (sm_80+ PTX; valid on compute_103)
// ---------------------------------------------------------------------------
__device__ __forceinline__ void mma_f16(float& d0, float& d1, float& d2, float& d3,
    uint32_t a0, uint32_t a1, uint32_t a2, uint32_t a3, uint32_t b0, uint32_t b1)
{
    asm volatile(
        "mma.sync.aligned.m16n8k16.row.col.f32.f16.f16.f32 "
        "{%0,%1,%2,%3},{%4,%5,%6,%7},{%8,%9},{%0,%1,%2,%3};"
        : "+f"(d0), "+f"(d1), "+f"(d2), "+f"(d3)
        : "r"(a0), "r"(a1), "r"(a2), "r"(a3), "r"(b0), "r"(b1));
}

__device__ __forceinline__ void ldsm_x4(uint32_t& r0, uint32_t& r1,
                                        uint32_t& r2, uint32_t& r3, uint32_t a)
{
    asm volatile("ldmatrix.sync.aligned.m8n8.x4.shared.b16 {%0,%1,%2,%3}, [%4];"
                 : "=r"(r0), "=r"(r1), "=r"(r2), "=r"(r3) : "r"(a));
}

__device__ __forceinline__ void ldsm_x4_t(uint32_t& r0, uint32_t& r1,
                                          uint32_t& r2, uint32_t& r3, uint32_t a)
{
    asm volatile("ldmatrix.sync.aligned.m8n8.x4.trans.shared.b16 {%0,%1,%2,%3}, [%4];"
                 : "=r"(r0), "=r"(r1), "=r"(r2), "=r"(r3) : "r"(a));
}

__device__ __forceinline__ uint32_t smem_u32(const void* p) {
    uint32_t a;
    asm("{ .reg .u64 t; cvta.to.shared.u64 t, %1; cvt.u32.u64 %0, t; }"
        : "=r"(a) : "l"(p));
    return a;
}

// pack (lo,hi) floats to f16x2 then exp2 in fp16 (MUFU.EX2 on both halves)
__device__ __forceinline__ uint32_t exp2_pack(float lo, float hi) {
    uint32_t r;
    asm("cvt.rn.f16x2.f32 %0, %1, %2;" : "=r"(r) : "f"(hi), "f"(lo));
    asm("ex2.approx.f16x2 %0, %0;" : "+r"(r));
    return r;
}

#define CP_ASYNC16(dst, src) \
    asm volatile("cp.async.cg.shared.global [%0], [%1], 16;" \
                 :: "r"(dst), "l"(src) : "memory")
#define CP_COMMIT() asm volatile("cp.async.commit_group;" ::: "memory")
#define CP_WAIT(n)  asm volatile("cp.async.wait_group %0;" :: "n"(n) : "memory")
#define BAR256()    asm volatile("bar.sync 0, 256;" ::: "memory")

// ---------------------------------------------------------------------------
// Split-fp16 GEMM (2-pass): C[M,N] = (Ah+Al)[M,K] @ Bh[N,K]^T
// 3 tiles/stage, 4-stage cp.async pipeline, XOR swizzle, one sync/stage,
// 2 CTAs/SM.
// ---------------------------------------------------------------------------
#define MM_TILE_B (128 * 64)                   // 8192 bytes per tile
#define MM_STAGE_B (3 * MM_TILE_B)             // 24576 per stage
#define MM_SMEM_BYTES (4 * MM_STAGE_B)         // 98304

__global__ __launch_bounds__(256, 2) void mm_gemm(
    const __half* __restrict__ Ah, const __half* __restrict__ Al,
    const __half* __restrict__ Bh,
    float* __restrict__ Cout, __half* __restrict__ Hout, int K, int ldc)
{
    extern __shared__ __half smd[];

    const int tid  = threadIdx.x;
    const int wid  = tid >> 5;
    const int lane = tid & 31;
    const int g8   = lane >> 2;
    const int t4   = lane & 3;
    const int m0   = blockIdx.y * 128;
    const int n0   = blockIdx.x * 128;
    const int ms   = wid & 3;
    const int ws   = wid >> 2;

    const int lrow  = (lane & 7) + ((lane >> 3) & 1) * 8;
    const int lcol8 = (lane >> 4) * 8;

    const __half* srcs[3] = {
        Ah + (size_t)m0 * K, Al + (size_t)m0 * K, Bh + (size_t)n0 * K };

    const int f_row = tid >> 2;
    const int f_ch  = tid & 3;

    uint32_t dsto[6];
    #pragma unroll
    for (int t = 0; t < 6; ++t) {
        const int tl  = t >> 1;
        const int row = ((t & 1) << 6) + f_row;
        const int cs  = f_ch ^ ((row >> 1) & 3);
        dsto[t] = (uint32_t)(((tl * 128 + row) * 32 + cs * 8) * 2);
    }
    const uint32_t smb0 = smem_u32(smd);

    auto issue_stage = [&](int s, int st) {
        const int k0 = s << 5;
        const uint32_t base = smb0 + (uint32_t)st * MM_STAGE_B;
        #pragma unroll
        for (int t = 0; t < 6; ++t) {
            const int tl  = t >> 1;
            const int row = ((t & 1) << 6) + f_row;
            const __half* src = srcs[tl] + (size_t)row * K + k0 + f_ch * 8;
            CP_ASYNC16(base + dsto[t], src);
        }
        CP_COMMIT();
    };

    float acc[2][8][4];
    #pragma unroll
    for (int mf = 0; mf < 2; mf++)
        #pragma unroll
        for (int nf = 0; nf < 8; nf++)
            #pragma unroll
            for (int i = 0; i < 4; i++) acc[mf][nf][i] = 0.f;

    const int nst = K >> 5;
    issue_stage(0, 0);
    if (nst > 1) issue_stage(1, 1);
    if (nst > 2) issue_stage(2, 2);

    int st = 0;
    for (int s = 0; s < nst; ++s) {
        if (s + 2 < nst)      CP_WAIT(2);
        else if (s + 1 < nst) CP_WAIT(1);
        else                  CP_WAIT(0);
        __syncthreads();
        if (s + 3 < nst) issue_stage(s + 3, (st + 3) & 3);

        const uint32_t smb = smb0 + (uint32_t)st * MM_STAGE_B;

        #pragma unroll
        for (int ks = 0; ks < 2; ++ks) {
            const int cb = ks * 2 + (lcol8 >> 3);

            uint32_t ah[2][4], al[2][4];
            #pragma unroll
            for (int mf = 0; mf < 2; ++mf) {
                const int row = ms * 32 + mf * 16 + lrow;
                const uint32_t off = (uint32_t)(row * 64
                                   + ((cb ^ ((row >> 1) & 3)) << 4));
                ldsm_x4(ah[mf][0], ah[mf][1], ah[mf][2], ah[mf][3],
                        smb + 0 * MM_TILE_B + off);
                ldsm_x4(al[mf][0], al[mf][1], al[mf][2], al[mf][3],
                        smb + 1 * MM_TILE_B + off);
            }

            #pragma unroll
            for (int np = 0; np < 4; ++np) {
                const int row = ws * 64 + np * 16 + lrow;
                const uint32_t off = (uint32_t)(row * 64
                                   + ((cb ^ ((row >> 1) & 3)) << 4));
                uint32_t bh[4];
                ldsm_x4(bh[0], bh[1], bh[2], bh[3], smb + 2 * MM_TILE_B + off);
                #pragma unroll
                for (int e = 0; e < 2; ++e) {
                    const int nf = np * 2 + e;
                    const uint32_t bh0 = bh[e], bh1 = bh[2 + e];
                    #pragma unroll
                    for (int mf = 0; mf < 2; ++mf) {
                        float* d = acc[mf][nf];
                        mma_f16(d[0], d[1], d[2], d[3],
                                ah[mf][0], ah[mf][1], ah[mf][2], ah[mf][3],
                                bh0, bh1);
                        mma_f16(d[0], d[1], d[2], d[3],
                                al[mf][0], al[mf][1], al[mf][2], al[mf][3],
                                bh0, bh1);
                    }
                }
            }
        }
        st = (st + 1) & 3;
    }

    #pragma unroll
    for (int mf = 0; mf < 2; ++mf) {
        const int r = m0 + ms * 32 + mf * 16 + g8;
        #pragma unroll
        for (int nf = 0; nf < 8; ++nf) {
            const int c = n0 + ws * 64 + nf * 8 + 2 * t4;
            *(float2*)(Cout + (size_t)r * ldc + c) =
                make_float2(acc[mf][nf][0], acc[mf][nf][1]);
            *(float2*)(Cout + (size_t)(r + 8) * ldc + c) =
                make_float2(acc[mf][nf][2], acc[mf][nf][3]);
            if (Hout) {
                *(__half2*)(Hout + (size_t)r * ldc + c) =
                    __floats2half2_rn(acc[mf][nf][0], acc[mf][nf][1]);
                *(__half2*)(Hout + (size_t)(r + 8) * ldc + c) =
                    __floats2half2_rn(acc[mf][nf][2], acc[mf][nf][3]);
            }
        }
    }
}

// ---------------------------------------------------------------------------
// Fused prep kernel (ONE launch): rope table + x split-fp16 + W^T pack.
// ---------------------------------------------------------------------------
#define PREP_ROPE_BLKS 256                       // T_*32/256
#define PREP_CVT_BLKS  4096                      // NT_*C_/4/256
#define PREP_PACK_BLKS ((C_/32)*(NQKV/32))       // 1792

__global__ void prep_all(const float* __restrict__ x,
                         const float* __restrict__ Wq,
                         const float* __restrict__ Wk,
                         const float* __restrict__ Wv)
{
    __shared__ float tile[32][33];
    const int bid = blockIdx.x;
    const int tid = threadIdx.x;

    if (bid < PREP_ROPE_BLKS) {
        const int i = bid * 256 + tid;
        const int t = i >> 5, lane = i & 31;
        const float inv = __expf(-(float)lane * 0.28782313662425574f);
        const float ang = (float)t * inv;
        float s, c;
        sincosf(ang, &s, &c);
        g_rope[i] = make_float2(c, s);
    } else if (bid < PREP_ROPE_BLKS + PREP_CVT_BLKS) {
        const int i = (bid - PREP_ROPE_BLKS) * 256 + tid;
        const float4 v = ((const float4*)x)[i];
        const __half h0 = __float2half(v.x);
        const __half h1 = __float2half(v.y);
        const __half h2 = __float2half(v.z);
        const __half h3 = __float2half(v.w);
        ((__half2*)g_xh)[2*i]   = __half2(h0, h1);
        ((__half2*)g_xh)[2*i+1] = __half2(h2, h3);
        ((__half2*)g_xl)[2*i] = __half2(
            __float2half(v.x - __half2float(h0)),
            __float2half(v.y - __half2float(h1)));
        ((__half2*)g_xl)[2*i+1] = __half2(
            __float2half(v.z - __half2float(h2)),
            __float2half(v.w - __half2float(h3)));
    } else {
        const int flat = bid - (PREP_ROPE_BLKS + PREP_CVT_BLKS);
        const int bx = flat % (C_ / 32);
        const int by = flat / (C_ / 32);
        const int tx = tid & 31, ty = tid >> 5;
        const int k0 = bx * 32;
        const int n0 = by * 32;

        const float* W; int nw, noff;
        if (n0 < KOFF)      { W = Wq; nw = H_*DQK_; noff = n0; }
        else if (n0 < VOFF) { W = Wk; nw = G_*DQK_; noff = n0 - KOFF; }
        else                { W = Wv; nw = G_*DV_;  noff = n0 - VOFF; }

        #pragma unroll
        for (int j = 0; j < 4; ++j)
            tile[ty + j * 8][tx] = W[(size_t)(k0 + ty + j * 8) * nw + noff + tx];
        __syncthreads();
        #pragma unroll
        for (int j = 0; j < 4; ++j)
            g_wth[(size_t)(n0 + ty + j * 8) * C_ + k0 + tx] =
                __float2half(tile[tx][ty + j * 8]);
    }
}

__global__ void pack_pt(const float* __restrict__ Wp)
{
    const int i = blockIdx.x * blockDim.x + threadIdx.x;
    if (i >= C_ * DV_) return;
    const int nn = i / DV_;
    const int k  = i % DV_;
    g_pth[i] = __float2half(Wp[(size_t)k * C_ + nn]);
}

__global__ void sum_split_y()
{
    const int i = blockIdx.x * blockDim.x + threadIdx.x;
    if (i >= (NT_ * DV_) / 4) return;
    float4 s = make_float4(0.f, 0.f, 0.f, 0.f);
    #pragma unroll
    for (int h = 0; h < H_; ++h) {
        const float4 v = ((const float4*)(g_yp + (size_t)h * NT_ * DV_))[i];
        s.x += v.x; s.y += v.y; s.z += v.z; s.w += v.w;
    }
    const __half h0 = __float2half(s.x);
    const __half h1 = __float2half(s.y);
    const __half h2 = __float2half(s.z);
    const __half h3 = __float2half(s.w);
    ((__half2*)g_yh)[2*i]   = __half2(h0, h1);
    ((__half2*)g_yh)[2*i+1] = __half2(h2, h3);
    ((__half2*)g_yl)[2*i] = __half2(
        __float2half(s.x - __half2float(h0)),
        __float2half(s.y - __half2float(h1)));
    ((__half2*)g_yl)[2*i+1] = __half2(
        __float2half(s.z - __half2float(h2)),
        __float2half(s.w - __half2float(h3)));
}

// ---------------------------------------------------------------------------
// RoPE + L2-norm; q scale folded with log2e (attention runs in exp2 domain).
// ---------------------------------------------------------------------------
__global__ void rope_norm_kernel(const float* __restrict__ qnf)
{
    const int warp = (blockIdx.x * blockDim.x + threadIdx.x) >> 5;
    const int lane = threadIdx.x & 31;
    if (warp >= NT_ * 20) return;
    const int token = warp / 20;
    const int slot  = warp % 20;
    const int t     = token & (T_ - 1);

    const size_t off = (size_t)token * NQKV
                     + ((slot < 16) ? slot * DQK_ : KOFF + (slot - 16) * DQK_);
    const float* src = g_qkv + off;
    __half* dst = g_qkvh + off;

    const float x0 = src[lane];
    const float x1 = src[lane + 32];

    const float2 cs = g_rope[(t << 5) + lane];
    const float c = cs.x, s = cs.y;

    const float r0 = x0 * c - x1 * s;
    const float r1 = x1 * c + x0 * s;

    float ss = r0 * r0 + r1 * r1;
    #pragma unroll
    for (int o = 16; o > 0; o >>= 1) ss += __shfl_xor_sync(0xFFFFFFFFu, ss, o);

    float scale = 1.f / (sqrtf(ss) + 1e-6f);
    if (slot < 16) scale *= qnf[0] * LOG2E_;

    dst[lane]      = __float2half(r0 * scale);
    dst[lane + 32] = __float2half(r1 * scale);
}

// ---------------------------------------------------------------------------
// Warp-specialized flash attention: 256 thr / 8 warps, 2 CTAs/SM.
// Warps 0-3 (softmax): QK^T mma + mask/max/exp + l; publish P (fp16 frags)
// and cr to double-buffered smem. Warps 4-7 (PV): rescale O, O += P V.
// K filled/waited by softmax warps, V by PV warps. One bar.sync 0,256 / iter.
// ---------------------------------------------------------------------------
struct AttnSmem {
    __half Qs[64][72];        // 9216
    __half Ks[2][64][72];     // 18432
    __half Vs[2][64][136];    // 34816
    __half Ps[2][64][72];     // 18432
    float  crs[2][64];        // 512
    float  invl[64];          // 256
};
#define ATTN_SMEM ((int)sizeof(AttnSmem))

__global__ __launch_bounds__(256, 2) void attn_kernel(const float* __restrict__ lobo)
{
    extern __shared__ char smem_raw[];
    AttnSmem& S = *reinterpret_cast<AttnSmem*>(smem_raw);

    const int tid  = threadIdx.x;
    const int wid  = tid >> 5;
    const int lane = tid & 31;
    const int g8   = lane >> 2;
    const int t4   = lane & 3;
    const bool producer = (wid < 4);
    const int rw    = producer ? wid : (wid - 4);   // row group 0..3
    const int rbase = rw << 4;

    const int qt = (gridDim.x - 1 - blockIdx.x);    // long blocks first
    const int h  = blockIdx.y;
    const int b  = blockIdx.z;
    const int gq = h >> 2;
    const int q0 = qt * 64;
    const size_t tokbase = (size_t)b * T_;
    const int nkt = qt + 1;

    // fragment addressing
    const int krow  = lane & 7;                      // K frags (non-trans)
    const int kcol8 = (lane >> 3) * 8;
    const int lrow  = (lane & 7) + ((lane >> 3) & 1) * 8;  // A/V frag rows
    const int lcol8 = (lane >> 4) * 8;

    // Fill Q tile (64 x 64 halves): all 256 threads, 8 half2 each
    #pragma unroll
    for (int i = 0; i < 8; ++i) {
        const int cid = tid + i * 256;
        const int row = cid >> 5;
        const int dp  = cid & 31;
        const uint32_t v = *(const uint32_t*)
            (g_qkvh + (tokbase + q0 + row) * NQKV + h * DQK_ + 2 * dp);
        *(uint32_t*)&S.Qs[row][2 * dp] = v;
    }

    if (producer) {
        // ---- softmax warps ----
        auto issue_k = [&](int kt) {
            const int st = kt & 1;
            const int k0 = kt * 64;
            #pragma unroll
            for (int j = 0; j < 4; ++j) {       // 64 rows x 128B, 128 threads
                const int idx = tid + j * 128;
                const int row = idx >> 3, c = idx & 7;
                CP_ASYNC16(smem_u32(&S.Ks[st][row][c * 8]),
                    g_qkvh + (tokbase + kt * 0 + k0 + row) * NQKV
                           + KOFF + gq * DQK_ + c * 8);
            }
            CP_COMMIT();
        };

        issue_k(0);
        CP_WAIT(0);                              // K(0) chunk arrived

        float m0 = lobo[h] * LOG2E_, m1 = m0;
        float l0 = 1.f, l1 = 1.f;
        uint32_t qf[4][4];
        const uint32_t ONES = 0x3C003C00u;

        for (int it = 0; it <= nkt; ++it) {
            BAR256();
            if (it >= nkt) continue;             // drain iteration(s)

            if (it + 1 < nkt) issue_k(it + 1);

            if (it == 0) {
                #pragma unroll
                for (int kf = 0; kf < 4; ++kf) {
                    const int cb = kf * 16 + 2 * t4;
                    qf[kf][0] = *(const uint32_t*)&S.Qs[rbase + g8    ][cb];
                    qf[kf][1] = *(const uint32_t*)&S.Qs[rbase + g8 + 8][cb];
                    qf[kf][2] = *(const uint32_t*)&S.Qs[rbase + g8    ][cb + 8];
                    qf[kf][3] = *(const uint32_t*)&S.Qs[rbase + g8 + 8][cb + 8];
                }
            }

            const int st = it & 1;
            // S = Q K^T
            float s[8][4];
            #pragma unroll
            for (int nf = 0; nf < 8; nf++)
                #pragma unroll
                for (int i = 0; i < 4; i++) s[nf][i] = 0.f;

            const uint32_t ksb = smem_u32(&S.Ks[st][0][0]);
            #pragma unroll
            for (int kp = 0; kp < 2; ++kp) {
                #pragma unroll
                for (int nf = 0; nf < 8; ++nf) {
                    uint32_t b0a, b1a, b0b, b1b;
                    ldsm_x4(b0a, b1a, b0b, b1b,
                            ksb + (uint32_t)(((nf * 8 + krow) * 72
                                              + kp * 32 + kcol8) * 2));
                    mma_f16(s[nf][0], s[nf][1], s[nf][2], s[nf][3],
                            qf[2*kp][0], qf[2*kp][1], qf[2*kp][2], qf[2*kp][3],
                            b0a, b1a);
                    mma_f16(s[nf][0], s[nf][1], s[nf][2], s[nf][3],
                            qf[2*kp+1][0], qf[2*kp+1][1], qf[2*kp+1][2],
                            qf[2*kp+1][3], b0b, b1b);
                }
            }

            const int rg0 = q0 + rbase + g8;
            const int rg1 = rg0 + 8;
            if (it == nkt - 1) {                 // diagonal tile
                const int k0 = it * 64;
                #pragma unroll
                for (int nf = 0; nf < 8; ++nf) {
                    const int c = k0 + nf * 8 + 2 * t4;
                    if (c     > rg0) s[nf][0] = -1e30f;
                    if (c + 1 > rg0) s[nf][1] = -1e30f;
                    if (c     > rg1) s[nf][2] = -1e30f;
                    if (c + 1 > rg1) s[nf][3] = -1e30f;
                }
            }

            float mx0 = -1e30f, mx1 = -1e30f;
            #pragma unroll
            for (int nf = 0; nf < 8; ++nf) {
                mx0 = fmaxf(mx0, fmaxf(s[nf][0], s[nf][1]));
                mx1 = fmaxf(mx1, fmaxf(s[nf][2], s[nf][3]));
            }
            mx0 = fmaxf(mx0, __shfl_xor_sync(0xFFFFFFFFu, mx0, 1));
            mx0 = fmaxf(mx0, __shfl_xor_sync(0xFFFFFFFFu, mx0, 2));
            mx1 = fmaxf(mx1, __shfl_xor_sync(0xFFFFFFFFu, mx1, 1));
            mx1 = fmaxf(mx1, __shfl_xor_sync(0xFFFFFFFFu, mx1, 2));

            const float mn0 = fmaxf(m0, mx0);
            const float mn1 = fmaxf(m1, mx1);
            const float cr0 = exp2f(m0 - mn0);
            const float cr1 = exp2f(m1 - mn1);
            m0 = mn0; m1 = mn1;

            uint32_t pa[8], pb[8];
            #pragma unroll
            for (int nf = 0; nf < 8; ++nf) {
                pa[nf] = exp2_pack(s[nf][0] - mn0, s[nf][1] - mn0);
                pb[nf] = exp2_pack(s[nf][2] - mn1, s[nf][3] - mn1);
            }

            // Row sums via ones-MMA
            float sf0 = 0.f, sf1 = 0.f, sf2 = 0.f, sf3 = 0.f;
            #pragma unroll
            for (int kf = 0; kf < 4; ++kf)
                mma_f16(sf0, sf1, sf2, sf3,
                        pa[2*kf], pb[2*kf], pa[2*kf+1], pb[2*kf+1], ONES, ONES);
            l0 = l0 * cr0 + sf0;
            l1 = l1 * cr1 + sf2;

            // Publish P fragments (canonical [row][key] layout) + cr
            #pragma unroll
            for (int nf = 0; nf < 8; ++nf) {
                *(uint32_t*)&S.Ps[st][rbase + g8    ][nf * 8 + 2 * t4] = pa[nf];
                *(uint32_t*)&S.Ps[st][rbase + g8 + 8][nf * 8 + 2 * t4] = pb[nf];
            }
            if (t4 == 0) {
                S.crs[st][rbase + g8]     = cr0;
                S.crs[st][rbase + g8 + 8] = cr1;
            }

            if (it + 1 < nkt) CP_WAIT(0);        // K(it+1) ready before next bar
        }

        // publish 1/l
        if (t4 == 0) {
            S.invl[rbase + g8]     = 1.f / l0;
            S.invl[rbase + g8 + 8] = 1.f / l1;
        }
        BAR256();
    } else {
        // ---- PV warps ----
        const int ctid = tid - 128;
        auto issue_v = [&](int kt) {
            const int st = kt & 1;
            const int k0 = kt * 64;
            #pragma unroll
            for (int j = 0; j < 8; ++j) {        // 64 rows x 256B, 128 threads
                const int idx = ctid + j * 128;
                const int row = idx >> 4, c = idx & 15;
                CP_ASYNC16(smem_u32(&S.Vs[st][row][c * 8]),
                    g_qkvh + (tokbase + k0 + row) * NQKV
                           + VOFF + gq * DV_ + c * 8);
            }
            CP_COMMIT();
        };

        float o[16][4];
        #pragma unroll
        for (int nf = 0; nf < 16; nf++)
            #pragma unroll
            for (int i = 0; i < 4; i++) o[nf][i] = 0.f;

        for (int it = 0; it <= nkt; ++it) {
            BAR256();
            if (it < nkt) issue_v(it);

            if (it >= 1) {
                const int pb = (it - 1) & 1;
                const float cr0 = S.crs[pb][rbase + g8];
                const float cr1 = S.crs[pb][rbase + g8 + 8];
                #pragma unroll
                for (int nf = 0; nf < 16; ++nf) {
                    o[nf][0] *= cr0; o[nf][1] *= cr0;
                    o[nf][2] *= cr1; o[nf][3] *= cr1;
                }

                const uint32_t psb = smem_u32(&S.Ps[pb][0][0]);
                const uint32_t vsb = smem_u32(&S.Vs[pb][0][0]);
                #pragma unroll
                for (int kf = 0; kf < 4; ++kf) {
                    uint32_t a0, a1, a2, a3;
                    ldsm_x4(a0, a1, a2, a3,
                            psb + (uint32_t)(((rbase + lrow) * 72
                                              + kf * 16 + lcol8) * 2));
                    #pragma unroll
                    for (int np = 0; np < 8; ++np) {
                        uint32_t b0, b1, b2, b3;
                        ldsm_x4_t(b0, b1, b2, b3,
                                  vsb + (uint32_t)(((kf * 16 + lrow) * 136
                                                    + np * 16 + lcol8) * 2));
                        mma_f16(o[2*np][0], o[2*np][1], o[2*np][2], o[2*np][3],
                                a0, a1, a2, a3, b0, b1);
                        mma_f16(o[2*np+1][0], o[2*np+1][1], o[2*np+1][2],
                                o[2*np+1][3], a0, a1, a2, a3, b2, b3);
                    }
                }
            }

            if (it < nkt) CP_WAIT(0);            // V(it) ready before next bar
        }

        BAR256();                                 // matches producer's final bar
        const float inv0 = S.invl[rbase + g8];
        const float inv1 = S.invl[rbase + g8 + 8];
        const int rg0 = q0 + rbase + g8;
        float* dst0 = g_yp + ((size_t)h * NT_ + tokbase + rg0) * DV_;
        float* dst1 = g_yp + ((size_t)h * NT_ + tokbase + rg0 + 8) * DV_;
        #pragma unroll
        for (int nf = 0; nf < 16; ++nf) {
            const int c = nf * 8 + 2 * t4;
            *(float2*)(dst0 + c) = make_float2(o[nf][0] * inv0, o[nf][1] * inv0);
            *(float2*)(dst1 + c) = make_float2(o[nf][2] * inv1, o[nf][3] * inv1);
        }
    }
}

// ---------------------------------------------------------------------------
// Launch (attn is the 4th launch -> lands in the ncu capture slot)
// ---------------------------------------------------------------------------
extern "C" void kernel_launch(void* const* d_in, const int* in_sizes, int n_in,
                              void* d_out, int out_size)
{
    const float* x     = (const float*)d_in[0];
    // d_in[1] = iter_num (unused)
    const float* Wq    = (const float*)d_in[2];
    const float* Wk    = (const float*)d_in[3];
    const float* Wv    = (const float*)d_in[4];
    const float* Wproj = (const float*)d_in[5];
    const float* lobo  = (const float*)d_in[6];
    const float* qnf   = (const float*)d_in[7];
    float* out = (float*)d_out;

    __half *xh, *xl, *wth, *yh, *yl, *pth, *qkvh_ptr;
    float *qkv_ptr;
    cudaGetSymbolAddress((void**)&xh, g_xh);
    cudaGetSymbolAddress((void**)&xl, g_xl);
    cudaGetSymbolAddress((void**)&wth, g_wth);
    cudaGetSymbolAddress((void**)&yh, g_yh);
    cudaGetSymbolAddress((void**)&yl, g_yl);
    cudaGetSymbolAddress((void**)&pth, g_pth);
    cudaGetSymbolAddress((void**)&qkv_ptr, g_qkv);
    cudaGetSymbolAddress((void**)&qkvh_ptr, g_qkvh);

    cudaFuncSetAttribute(mm_gemm, cudaFuncAttributeMaxDynamicSharedMemorySize,
                         MM_SMEM_BYTES);
    cudaFuncSetAttribute(attn_kernel, cudaFuncAttributeMaxDynamicSharedMemorySize,
                         ATTN_SMEM);

    // 1: fused prep (rope table + x split + W^T pack)
    prep_all<<<PREP_ROPE_BLKS + PREP_CVT_BLKS + PREP_PACK_BLKS, 256>>>(
        x, Wq, Wk, Wv);

    // 2: fused QKV projection -> fp32 g_qkv + fp16 mirror
    mm_gemm<<<dim3(NQKV / 128, NT_ / 128), 256, MM_SMEM_BYTES>>>(
        xh, xl, wth, qkv_ptr, qkvh_ptr, C_, NQKV);

    // 3: RoPE + qk-norm + logit scale (base-2) -> fp16 q/k
    rope_norm_kernel<<<(NT_ * 20) / 8, 256>>>(qnf);

    // 4: attention (warp-specialized)  (ncu capture slot)
    attn_kernel<<<dim3(T_ / 64, H_, B_), 256, ATTN_SMEM>>>(lobo);

    // 5-7: proj weight pack, head-sum, output projection
    pack_pt<<<(C_ * DV_ + 255) / 256, 256>>>(Wproj);
    sum_split_y<<<(NT_ * DV_ / 4 + 255) / 256, 256>>>();
    mm_gemm<<<dim3(C_ / 128, NT_ / 128), 256, MM_SMEM_BYTES>>>(
        yh, yl, pth, out, nullptr, DV_, C_);
}

// round 17
// speedup vs baseline: 1.0241x; 1.0236x over previous
#include <cuda_runtime.h>
#include <cuda_bf16.h>
#include <cuda_fp16.h>
#include <math.h>
#include <stdint.h>

// Problem constants
#define B_   2
#define T_   2048
#define C_   1024
#define H_   16
#define G_   4
#define DQK_ 64
#define DV_  128
#define NT_  (B_ * T_)        // 4096 tokens
#define NQKV (H_*DQK_ + G_*DQK_ + G_*DV_)   // 1792
#define KOFF (H_*DQK_)        // 1024
#define VOFF (H_*DQK_ + G_*DQK_) // 1280
#define LOG2E_ 1.4426950408889634f

// ---------------------------------------------------------------------------
// Device scratch (no cudaMalloc allowed)
// ---------------------------------------------------------------------------
__device__ __half g_xh[(size_t)NT_ * C_];      // x split-fp16 hi
__device__ __half g_xl[(size_t)NT_ * C_];      // x split-fp16 lo
__device__ __half g_wth[(size_t)NQKV * C_];    // packed W^T [1792][1024] fp16
__device__ __half g_yh[(size_t)NT_ * DV_];     // head-summed attn out fp16
__device__ __half g_pth[(size_t)C_ * DV_];     // Wproj^T [1024][128] fp16
__device__ float  g_qkv[(size_t)NT_ * NQKV];   // fused projection (fp32)
__device__ __half g_qkvh[(size_t)NT_ * NQKV];  // fp16 q(roped)/k(roped)/v
__device__ float  g_yp[(size_t)H_ * NT_ * DV_];// per-head attn output
__device__ float2 g_rope[(size_t)T_ * 32];     // (cos,sin) per (t,lane)

// ---------------------------------------------------------------------------
// mma.sync / ldmatrix / cp.async helpers (sm_80+ PTX; valid on compute_103)
// ---------------------------------------------------------------------------
__device__ __forceinline__ void mma_f16(float& d0, float& d1, float& d2, float& d3,
    uint32_t a0, uint32_t a1, uint32_t a2, uint32_t a3, uint32_t b0, uint32_t b1)
{
    asm volatile(
        "mma.sync.aligned.m16n8k16.row.col.f32.f16.f16.f32 "
        "{%0,%1,%2,%3},{%4,%5,%6,%7},{%8,%9},{%0,%1,%2,%3};"
        : "+f"(d0), "+f"(d1), "+f"(d2), "+f"(d3)
        : "r"(a0), "r"(a1), "r"(a2), "r"(a3), "r"(b0), "r"(b1));
}

__device__ __forceinline__ void ldsm_x4(uint32_t& r0, uint32_t& r1,
                                        uint32_t& r2, uint32_t& r3, uint32_t a)
{
    asm volatile("ldmatrix.sync.aligned.m8n8.x4.shared.b16 {%0,%1,%2,%3}, [%4];"
                 : "=r"(r0), "=r"(r1), "=r"(r2), "=r"(r3) : "r"(a));
}

__device__ __forceinline__ void ldsm_x4_t(uint32_t& r0, uint32_t& r1,
                                          uint32_t& r2, uint32_t& r3, uint32_t a)
{
    asm volatile("ldmatrix.sync.aligned.m8n8.x4.trans.shared.b16 {%0,%1,%2,%3}, [%4];"
                 : "=r"(r0), "=r"(r1), "=r"(r2), "=r"(r3) : "r"(a));
}

__device__ __forceinline__ uint32_t smem_u32(const void* p) {
    uint32_t a;
    asm("{ .reg .u64 t; cvta.to.shared.u64 t, %1; cvt.u32.u64 %0, t; }"
        : "=r"(a) : "l"(p));
    return a;
}

// pack (lo,hi) floats to f16x2 then exp2 in fp16 (MUFU.EX2 on both halves)
__device__ __forceinline__ uint32_t exp2_pack(float lo, float hi) {
    uint32_t r;
    asm("cvt.rn.f16x2.f32 %0, %1, %2;" : "=r"(r) : "f"(hi), "f"(lo));
    asm("ex2.approx.f16x2 %0, %0;" : "+r"(r));
    return r;
}

#define CP_ASYNC16(dst, src) \
    asm volatile("cp.async.cg.shared.global [%0], [%1], 16;" \
                 :: "r"(dst), "l"(src) : "memory")
#define CP_COMMIT() asm volatile("cp.async.commit_group;" ::: "memory")
#define CP_WAIT(n)  asm volatile("cp.async.wait_group %0;" :: "n"(n) : "memory")
#define BAR256()    asm volatile("bar.sync 0, 256;" ::: "memory")

// ---------------------------------------------------------------------------
// Split-fp16 GEMM: C[M,N] = (Ah[+Al])[M,K] @ Bh[N,K]^T
// The Al (low-bits) pass runs only for output columns n0 < nlo — columns at
// or beyond nlo get plain-fp16 A (used for V outputs / the 1-pass proj).
// 3 tiles/stage, 4-stage cp.async pipeline, XOR swizzle, one sync/stage,
// 2 CTAs/SM.
// ---------------------------------------------------------------------------
#define MM_TILE_B (128 * 64)                   // 8192 bytes per tile
#define MM_STAGE_B (3 * MM_TILE_B)             // 24576 per stage
#define MM_SMEM_BYTES (4 * MM_STAGE_B)         // 98304

__global__ __launch_bounds__(256, 2) void mm_gemm(
    const __half* __restrict__ Ah, const __half* __restrict__ Al,
    const __half* __restrict__ Bh,
    float* __restrict__ Cout, __half* __restrict__ Hout, int K, int ldc,
    int nlo)
{
    extern __shared__ __half smd[];

    const int tid  = threadIdx.x;
    const int wid  = tid >> 5;
    const int lane = tid & 31;
    const int g8   = lane >> 2;
    const int t4   = lane & 3;
    const int m0   = blockIdx.y * 128;
    const int n0   = blockIdx.x * 128;
    const int ms   = wid & 3;
    const int ws   = wid >> 2;
    const bool use_lo = (n0 < nlo);

    const int lrow  = (lane & 7) + ((lane >> 3) & 1) * 8;
    const int lcol8 = (lane >> 4) * 8;

    const __half* srcs[3] = {
        Ah + (size_t)m0 * K, Al + (size_t)m0 * K, Bh + (size_t)n0 * K };

    const int f_row = tid >> 2;
    const int f_ch  = tid & 3;

    uint32_t dsto[6];
    #pragma unroll
    for (int t = 0; t < 6; ++t) {
        const int tl  = t >> 1;
        const int row = ((t & 1) << 6) + f_row;
        const int cs  = f_ch ^ ((row >> 1) & 3);
        dsto[t] = (uint32_t)(((tl * 128 + row) * 32 + cs * 8) * 2);
    }
    const uint32_t smb0 = smem_u32(smd);

    auto issue_stage = [&](int s, int st) {
        const int k0 = s << 5;
        const uint32_t base = smb0 + (uint32_t)st * MM_STAGE_B;
        #pragma unroll
        for (int t = 0; t < 6; ++t) {
            if ((t == 2 || t == 3) && !use_lo) continue;   // skip Al fill
            const int tl  = t >> 1;
            const int row = ((t & 1) << 6) + f_row;
            const __half* src = srcs[tl] + (size_t)row * K + k0 + f_ch * 8;
            CP_ASYNC16(base + dsto[t], src);
        }
        CP_COMMIT();
    };

    float acc[2][8][4];
    #pragma unroll
    for (int mf = 0; mf < 2; mf++)
        #pragma unroll
        for (int nf = 0; nf < 8; nf++)
            #pragma unroll
            for (int i = 0; i < 4; i++) acc[mf][nf][i] = 0.f;

    const int nst = K >> 5;
    issue_stage(0, 0);
    if (nst > 1) issue_stage(1, 1);
    if (nst > 2) issue_stage(2, 2);

    int st = 0;
    for (int s = 0; s < nst; ++s) {
        if (s + 2 < nst)      CP_WAIT(2);
        else if (s + 1 < nst) CP_WAIT(1);
        else                  CP_WAIT(0);
        __syncthreads();
        if (s + 3 < nst) issue_stage(s + 3, (st + 3) & 3);

        const uint32_t smb = smb0 + (uint32_t)st * MM_STAGE_B;

        #pragma unroll
        for (int ks = 0; ks < 2; ++ks) {
            const int cb = ks * 2 + (lcol8 >> 3);

            uint32_t ah[2][4], al[2][4];
            #pragma unroll
            for (int mf = 0; mf < 2; ++mf) {
                const int row = ms * 32 + mf * 16 + lrow;
                const uint32_t off = (uint32_t)(row * 64
                                   + ((cb ^ ((row >> 1) & 3)) << 4));
                ldsm_x4(ah[mf][0], ah[mf][1], ah[mf][2], ah[mf][3],
                        smb + 0 * MM_TILE_B + off);
                if (use_lo)
                    ldsm_x4(al[mf][0], al[mf][1], al[mf][2], al[mf][3],
                            smb + 1 * MM_TILE_B + off);
            }

            #pragma unroll
            for (int np = 0; np < 4; ++np) {
                const int row = ws * 64 + np * 16 + lrow;
                const uint32_t off = (uint32_t)(row * 64
                                   + ((cb ^ ((row >> 1) & 3)) << 4));
                uint32_t bh[4];
                ldsm_x4(bh[0], bh[1], bh[2], bh[3], smb + 2 * MM_TILE_B + off);
                #pragma unroll
                for (int e = 0; e < 2; ++e) {
                    const int nf = np * 2 + e;
                    const uint32_t bh0 = bh[e], bh1 = bh[2 + e];
                    #pragma unroll
                    for (int mf = 0; mf < 2; ++mf) {
                        float* d = acc[mf][nf];
                        mma_f16(d[0], d[1], d[2], d[3],
                                ah[mf][0], ah[mf][1], ah[mf][2], ah[mf][3],
                                bh0, bh1);
                        if (use_lo)
                            mma_f16(d[0], d[1], d[2], d[3],
                                    al[mf][0], al[mf][1], al[mf][2], al[mf][3],
                                    bh0, bh1);
                    }
                }
            }
        }
        st = (st + 1) & 3;
    }

    #pragma unroll
    for (int mf = 0; mf < 2; ++mf) {
        const int r = m0 + ms * 32 + mf * 16 + g8;
        #pragma unroll
        for (int nf = 0; nf < 8; ++nf) {
            const int c = n0 + ws * 64 + nf * 8 + 2 * t4;
            *(float2*)(Cout + (size_t)r * ldc + c) =
                make_float2(acc[mf][nf][0], acc[mf][nf][1]);
            *(float2*)(Cout + (size_t)(r + 8) * ldc + c) =
                make_float2(acc[mf][nf][2], acc[mf][nf][3]);
            if (Hout) {
                *(__half2*)(Hout + (size_t)r * ldc + c) =
                    __floats2half2_rn(acc[mf][nf][0], acc[mf][nf][1]);
                *(__half2*)(Hout + (size_t)(r + 8) * ldc + c) =
                    __floats2half2_rn(acc[mf][nf][2], acc[mf][nf][3]);
            }
        }
    }
}

// ---------------------------------------------------------------------------
// Fused prep kernel (ONE launch): rope table + x split + W^T pack + Wproj^T.
// ---------------------------------------------------------------------------
#define PREP_ROPE_BLKS 256                       // T_*32/256
#define PREP_CVT_BLKS  4096                      // NT_*C_/4/256
#define PREP_PACK_BLKS ((C_/32)*(NQKV/32))       // 1792
#define PREP_PT_BLKS   ((C_*DV_)/256)            // 512

__global__ void prep_all(const float* __restrict__ x,
                         const float* __restrict__ Wq,
                         const float* __restrict__ Wk,
                         const float* __restrict__ Wv,
                         const float* __restrict__ Wp)
{
    __shared__ float tile[32][33];
    const int bid = blockIdx.x;
    const int tid = threadIdx.x;

    if (bid < PREP_ROPE_BLKS) {
        const int i = bid * 256 + tid;
        const int t = i >> 5, lane = i & 31;
        const float inv = __expf(-(float)lane * 0.28782313662425574f);
        const float ang = (float)t * inv;
        float s, c;
        sincosf(ang, &s, &c);
        g_rope[i] = make_float2(c, s);
    } else if (bid < PREP_ROPE_BLKS + PREP_CVT_BLKS) {
        const int i = (bid - PREP_ROPE_BLKS) * 256 + tid;
        const float4 v = ((const float4*)x)[i];
        const __half h0 = __float2half(v.x);
        const __half h1 = __float2half(v.y);
        const __half h2 = __float2half(v.z);
        const __half h3 = __float2half(v.w);
        ((__half2*)g_xh)[2*i]   = __half2(h0, h1);
        ((__half2*)g_xh)[2*i+1] = __half2(h2, h3);
        ((__half2*)g_xl)[2*i] = __half2(
            __float2half(v.x - __half2float(h0)),
            __float2half(v.y - __half2float(h1)));
        ((__half2*)g_xl)[2*i+1] = __half2(
            __float2half(v.z - __half2float(h2)),
            __float2half(v.w - __half2float(h3)));
    } else if (bid < PREP_ROPE_BLKS + PREP_CVT_BLKS + PREP_PACK_BLKS) {
        const int flat = bid - (PREP_ROPE_BLKS + PREP_CVT_BLKS);
        const int bx = flat % (C_ / 32);
        const int by = flat / (C_ / 32);
        const int tx = tid & 31, ty = tid >> 5;
        const int k0 = bx * 32;
        const int n0 = by * 32;

        const float* W; int nw, noff;
        if (n0 < KOFF)      { W = Wq; nw = H_*DQK_; noff = n0; }
        else if (n0 < VOFF) { W = Wk; nw = G_*DQK_; noff = n0 - KOFF; }
        else                { W = Wv; nw = G_*DV_;  noff = n0 - VOFF; }

        #pragma unroll
        for (int j = 0; j < 4; ++j)
            tile[ty + j * 8][tx] = W[(size_t)(k0 + ty + j * 8) * nw + noff + tx];
        __syncthreads();
        #pragma unroll
        for (int j = 0; j < 4; ++j)
            g_wth[(size_t)(n0 + ty + j * 8) * C_ + k0 + tx] =
                __float2half(tile[tx][ty + j * 8]);
    } else {
        const int i = (bid - (PREP_ROPE_BLKS + PREP_CVT_BLKS + PREP_PACK_BLKS))
                      * 256 + tid;
        const int nn = i / DV_;
        const int k  = i % DV_;
        g_pth[i] = __float2half(Wp[(size_t)k * C_ + nn]);
    }
}

// Head-sum + fp16 of attention output, 4 elems/thread (1-pass proj input)
__global__ void sum_split_y()
{
    const int i = blockIdx.x * blockDim.x + threadIdx.x;
    if (i >= (NT_ * DV_) / 4) return;
    float4 s = make_float4(0.f, 0.f, 0.f, 0.f);
    #pragma unroll
    for (int h = 0; h < H_; ++h) {
        const float4 v = ((const float4*)(g_yp + (size_t)h * NT_ * DV_))[i];
        s.x += v.x; s.y += v.y; s.z += v.z; s.w += v.w;
    }
    ((__half2*)g_yh)[2*i]   = __floats2half2_rn(s.x, s.y);
    ((__half2*)g_yh)[2*i+1] = __floats2half2_rn(s.z, s.w);
}

// ---------------------------------------------------------------------------
// RoPE + L2-norm; q scale folded with log2e (attention runs in exp2 domain).
// ---------------------------------------------------------------------------
__global__ void rope_norm_kernel(const float* __restrict__ qnf)
{
    const int warp = (blockIdx.x * blockDim.x + threadIdx.x) >> 5;
    const int lane = threadIdx.x & 31;
    if (warp >= NT_ * 20) return;
    const int token = warp / 20;
    const int slot  = warp % 20;
    const int t     = token & (T_ - 1);

    const size_t off = (size_t)token * NQKV
                     + ((slot < 16) ? slot * DQK_ : KOFF + (slot - 16) * DQK_);
    const float* src = g_qkv + off;
    __half* dst = g_qkvh + off;

    const float x0 = src[lane];
    const float x1 = src[lane + 32];

    const float2 cs = g_rope[(t << 5) + lane];
    const float c = cs.x, s = cs.y;

    const float r0 = x0 * c - x1 * s;
    const float r1 = x1 * c + x0 * s;

    float ss = r0 * r0 + r1 * r1;
    #pragma unroll
    for (int o = 16; o > 0; o >>= 1) ss += __shfl_xor_sync(0xFFFFFFFFu, ss, o);

    float scale = 1.f / (sqrtf(ss) + 1e-6f);
    if (slot < 16) scale *= qnf[0] * LOG2E_;

    dst[lane]      = __float2half(r0 * scale);
    dst[lane + 32] = __float2half(r1 * scale);
}

// ---------------------------------------------------------------------------
// Warp-specialized flash attention (unchanged from round 16): 256 thr /
// 8 warps, 2 CTAs/SM. Warps 0-3: QK^T + softmax, publish P + cr; warps 4-7:
// PV with O accumulators. One bar.sync 0,256 per iteration.
// ---------------------------------------------------------------------------
struct AttnSmem {
    __half Qs[64][72];        // 9216
    __half Ks[2][64][72];     // 18432
    __half Vs[2][64][136];    // 34816
    __half Ps[2][64][72];     // 18432
    float  crs[2][64];        // 512
    float  invl[64];          // 256
};
#define ATTN_SMEM ((int)sizeof(AttnSmem))

__global__ __launch_bounds__(256, 2) void attn_kernel(const float* __restrict__ lobo)
{
    extern __shared__ char smem_raw[];
    AttnSmem& S = *reinterpret_cast<AttnSmem*>(smem_raw);

    const int tid  = threadIdx.x;
    const int wid  = tid >> 5;
    const int lane = tid & 31;
    const int g8   = lane >> 2;
    const int t4   = lane & 3;
    const bool producer = (wid < 4);
    const int rw    = producer ? wid : (wid - 4);
    const int rbase = rw << 4;

    const int qt = (gridDim.x - 1 - blockIdx.x);
    const int h  = blockIdx.y;
    const int b  = blockIdx.z;
    const int gq = h >> 2;
    const int q0 = qt * 64;
    const size_t tokbase = (size_t)b * T_;
    const int nkt = qt + 1;

    const int krow  = lane & 7;
    const int kcol8 = (lane >> 3) * 8;
    const int lrow  = (lane & 7) + ((lane >> 3) & 1) * 8;
    const int lcol8 = (lane >> 4) * 8;

    #pragma unroll
    for (int i = 0; i < 8; ++i) {
        const int cid = tid + i * 256;
        const int row = cid >> 5;
        const int dp  = cid & 31;
        const uint32_t v = *(const uint32_t*)
            (g_qkvh + (tokbase + q0 + row) * NQKV + h * DQK_ + 2 * dp);
        *(uint32_t*)&S.Qs[row][2 * dp] = v;
    }

    if (producer) {
        auto issue_k = [&](int kt) {
            const int st = kt & 1;
            const int k0 = kt * 64;
            #pragma unroll
            for (int j = 0; j < 4; ++j) {
                const int idx = tid + j * 128;
                const int row = idx >> 3, c = idx & 7;
                CP_ASYNC16(smem_u32(&S.Ks[st][row][c * 8]),
                    g_qkvh + (tokbase + k0 + row) * NQKV
                           + KOFF + gq * DQK_ + c * 8);
            }
            CP_COMMIT();
        };

        issue_k(0);
        CP_WAIT(0);

        float m0 = lobo[h] * LOG2E_, m1 = m0;
        float l0 = 1.f, l1 = 1.f;
        uint32_t qf[4][4];
        const uint32_t ONES = 0x3C003C00u;

        for (int it = 0; it <= nkt; ++it) {
            BAR256();
            if (it >= nkt) continue;

            if (it + 1 < nkt) issue_k(it + 1);

            if (it == 0) {
                #pragma unroll
                for (int kf = 0; kf < 4; ++kf) {
                    const int cb = kf * 16 + 2 * t4;
                    qf[kf][0] = *(const uint32_t*)&S.Qs[rbase + g8    ][cb];
                    qf[kf][1] = *(const uint32_t*)&S.Qs[rbase + g8 + 8][cb];
                    qf[kf][2] = *(const uint32_t*)&S.Qs[rbase + g8    ][cb + 8];
                    qf[kf][3] = *(const uint32_t*)&S.Qs[rbase + g8 + 8][cb + 8];
                }
            }

            const int st = it & 1;
            float s[8][4];
            #pragma unroll
            for (int nf = 0; nf < 8; nf++)
                #pragma unroll
                for (int i = 0; i < 4; i++) s[nf][i] = 0.f;

            const uint32_t ksb = smem_u32(&S.Ks[st][0][0]);
            #pragma unroll
            for (int kp = 0; kp < 2; ++kp) {
                #pragma unroll
                for (int nf = 0; nf < 8; ++nf) {
                    uint32_t b0a, b1a, b0b, b1b;
                    ldsm_x4(b0a, b1a, b0b, b1b,
                            ksb + (uint32_t)(((nf * 8 + krow) * 72
                                              + kp * 32 + kcol8) * 2));
                    mma_f16(s[nf][0], s[nf][1], s[nf][2], s[nf][3],
                            qf[2*kp][0], qf[2*kp][1], qf[2*kp][2], qf[2*kp][3],
                            b0a, b1a);
                    mma_f16(s[nf][0], s[nf][1], s[nf][2], s[nf][3],
                            qf[2*kp+1][0], qf[2*kp+1][1], qf[2*kp+1][2],
                            qf[2*kp+1][3], b0b, b1b);
                }
            }

            const int rg0 = q0 + rbase + g8;
            const int rg1 = rg0 + 8;
            if (it == nkt - 1) {
                const int k0 = it * 64;
                #pragma unroll
                for (int nf = 0; nf < 8; ++nf) {
                    const int c = k0 + nf * 8 + 2 * t4;
                    if (c     > rg0) s[nf][0] = -1e30f;
                    if (c + 1 > rg0) s[nf][1] = -1e30f;
                    if (c     > rg1) s[nf][2] = -1e30f;
                    if (c + 1 > rg1) s[nf][3] = -1e30f;
                }
            }

            float mx0 = -1e30f, mx1 = -1e30f;
            #pragma unroll
            for (int nf = 0; nf < 8; ++nf) {
                mx0 = fmaxf(mx0, fmaxf(s[nf][0], s[nf][1]));
                mx1 = fmaxf(mx1, fmaxf(s[nf][2], s[nf][3]));
            }
            mx0 = fmaxf(mx0, __shfl_xor_sync(0xFFFFFFFFu, mx0, 1));
            mx0 = fmaxf(mx0, __shfl_xor_sync(0xFFFFFFFFu, mx0, 2));
            mx1 = fmaxf(mx1, __shfl_xor_sync(0xFFFFFFFFu, mx1, 1));
            mx1 = fmaxf(mx1, __shfl_xor_sync(0xFFFFFFFFu, mx1, 2));

            const float mn0 = fmaxf(m0, mx0);
            const float mn1 = fmaxf(m1, mx1);
            const float cr0 = exp2f(m0 - mn0);
            const float cr1 = exp2f(m1 - mn1);
            m0 = mn0; m1 = mn1;

            uint32_t pa[8], pb[8];
            #pragma unroll
            for (int nf = 0; nf < 8; ++nf) {
                pa[nf] = exp2_pack(s[nf][0] - mn0, s[nf][1] - mn0);
                pb[nf] = exp2_pack(s[nf][2] - mn1, s[nf][3] - mn1);
            }

            float sf0 = 0.f, sf1 = 0.f, sf2 = 0.f, sf3 = 0.f;
            #pragma unroll
            for (int kf = 0; kf < 4; ++kf)
                mma_f16(sf0, sf1, sf2, sf3,
                        pa[2*kf], pb[2*kf], pa[2*kf+1], pb[2*kf+1], ONES, ONES);
            l0 = l0 * cr0 + sf0;
            l1 = l1 * cr1 + sf2;

            #pragma unroll
            for (int nf = 0; nf < 8; ++nf) {
                *(uint32_t*)&S.Ps[st][rbase + g8    ][nf * 8 + 2 * t4] = pa[nf];
                *(uint32_t*)&S.Ps[st][rbase + g8 + 8][nf * 8 + 2 * t4] = pb[nf];
            }
            if (t4 == 0) {
                S.crs[st][rbase + g8]     = cr0;
                S.crs[st][rbase + g8 + 8] = cr1;
            }

            if (it + 1 < nkt) CP_WAIT(0);
        }

        if (t4 == 0) {
            S.invl[rbase + g8]     = 1.f / l0;
            S.invl[rbase + g8 + 8] = 1.f / l1;
        }
        BAR256();
    } else {
        const int ctid = tid - 128;
        auto issue_v = [&](int kt) {
            const int st = kt & 1;
            const int k0 = kt * 64;
            #pragma unroll
            for (int j = 0; j < 8; ++j) {
                const int idx = ctid + j * 128;
                const int row = idx >> 4, c = idx & 15;
                CP_ASYNC16(smem_u32(&S.Vs[st][row][c * 8]),
                    g_qkvh + (tokbase + k0 + row) * NQKV
                           + VOFF + gq * DV_ + c * 8);
            }
            CP_COMMIT();
        };

        float o[16][4];
        #pragma unroll
        for (int nf = 0; nf < 16; nf++)
            #pragma unroll
            for (int i = 0; i < 4; i++) o[nf][i] = 0.f;

        for (int it = 0; it <= nkt; ++it) {
            BAR256();
            if (it < nkt) issue_v(it);

            if (it >= 1) {
                const int pb = (it - 1) & 1;
                const float cr0 = S.crs[pb][rbase + g8];
                const float cr1 = S.crs[pb][rbase + g8 + 8];
                #pragma unroll
                for (int nf = 0; nf < 16; ++nf) {
                    o[nf][0] *= cr0; o[nf][1] *= cr0;
                    o[nf][2] *= cr1; o[nf][3] *= cr1;
                }

                const uint32_t psb = smem_u32(&S.Ps[pb][0][0]);
                const uint32_t vsb = smem_u32(&S.Vs[pb][0][0]);
                #pragma unroll
                for (int kf = 0; kf < 4; ++kf) {
                    uint32_t a0, a1, a2, a3;
                    ldsm_x4(a0, a1, a2, a3,
                            psb + (uint32_t)(((rbase + lrow) * 72
                                              + kf * 16 + lcol8) * 2));
                    #pragma unroll
                    for (int np = 0; np < 8; ++np) {
                        uint32_t b0, b1, b2, b3;
                        ldsm_x4_t(b0, b1, b2, b3,
                                  vsb + (uint32_t)(((kf * 16 + lrow) * 136
                                                    + np * 16 + lcol8) * 2));
                        mma_f16(o[2*np][0], o[2*np][1], o[2*np][2], o[2*np][3],
                                a0, a1, a2, a3, b0, b1);
                        mma_f16(o[2*np+1][0], o[2*np+1][1], o[2*np+1][2],
                                o[2*np+1][3], a0, a1, a2, a3, b2, b3);
                    }
                }
            }

            if (it < nkt) CP_WAIT(0);
        }

        BAR256();
        const float inv0 = S.invl[rbase + g8];
        const float inv1 = S.invl[rbase + g8 + 8];
        const int rg0 = q0 + rbase + g8;
        float* dst0 = g_yp + ((size_t)h * NT_ + tokbase + rg0) * DV_;
        float* dst1 = g_yp + ((size_t)h * NT_ + tokbase + rg0 + 8) * DV_;
        #pragma unroll
        for (int nf = 0; nf < 16; ++nf) {
            const int c = nf * 8 + 2 * t4;
            *(float2*)(dst0 + c) = make_float2(o[nf][0] * inv0, o[nf][1] * inv0);
            *(float2*)(dst1 + c) = make_float2(o[nf][2] * inv1, o[nf][3] * inv1);
        }
    }
}

// ---------------------------------------------------------------------------
// Launch (attn is the 4th launch -> lands in the ncu capture slot)
// ---------------------------------------------------------------------------
extern "C" void kernel_launch(void* const* d_in, const int* in_sizes, int n_in,
                              void* d_out, int out_size)
{
    const float* x     = (const float*)d_in[0];
    // d_in[1] = iter_num (unused)
    const float* Wq    = (const float*)d_in[2];
    const float* Wk    = (const float*)d_in[3];
    const float* Wv    = (const float*)d_in[4];
    const float* Wproj = (const float*)d_in[5];
    const float* lobo  = (const float*)d_in[6];
    const float* qnf   = (const float*)d_in[7];
    float* out = (float*)d_out;

    __half *xh, *xl, *wth, *yh, *pth, *qkvh_ptr;
    float *qkv_ptr;
    cudaGetSymbolAddress((void**)&xh, g_xh);
    cudaGetSymbolAddress((void**)&xl, g_xl);
    cudaGetSymbolAddress((void**)&wth, g_wth);
    cudaGetSymbolAddress((void**)&yh, g_yh);
    cudaGetSymbolAddress((void**)&pth, g_pth);
    cudaGetSymbolAddress((void**)&qkv_ptr, g_qkv);
    cudaGetSymbolAddress((void**)&qkvh_ptr, g_qkvh);

    cudaFuncSetAttribute(mm_gemm, cudaFuncAttributeMaxDynamicSharedMemorySize,
                         MM_SMEM_BYTES);
    cudaFuncSetAttribute(attn_kernel, cudaFuncAttributeMaxDynamicSharedMemorySize,
                         ATTN_SMEM);

    // 1: fused prep (rope table + x split + W^T pack + Wproj^T pack)
    prep_all<<<PREP_ROPE_BLKS + PREP_CVT_BLKS + PREP_PACK_BLKS + PREP_PT_BLKS,
               256>>>(x, Wq, Wk, Wv, Wproj);

    // 2: fused QKV projection -> fp32 g_qkv + fp16 mirror; lo-pass only for
    //    q/k columns (n < VOFF); V columns are fp16-bound anyway
    mm_gemm<<<dim3(NQKV / 128, NT_ / 128), 256, MM_SMEM_BYTES>>>(
        xh, xl, wth, qkv_ptr, qkvh_ptr, C_, NQKV, VOFF);

    // 3: RoPE + qk-norm + logit scale (base-2) -> fp16 q/k
    rope_norm_kernel<<<(NT_ * 20) / 8, 256>>>(qnf);

    // 4: attention (warp-specialized)  (ncu capture slot)
    attn_kernel<<<dim3(T_ / 64, H_, B_), 256, ATTN_SMEM>>>(lobo);

    // 5-6: head-sum (fp16), 1-pass output projection
    sum_split_y<<<(NT_ * DV_ / 4 + 255) / 256, 256>>>();
    mm_gemm<<<dim3(C_ / 128, NT_ / 128), 256, MM_SMEM_BYTES>>>(
        yh, yh, pth, out, nullptr, DV_, C_, 0);
}